// round 2
// baseline (speedup 1.0000x reference)
#include <cuda_runtime.h>

#define N_ROWS 32768
#define C_DIM  512
#define NE     8192
#define HW     4096
#define TM     128
#define TN     128
#define KB     16
#define BETA_F 0.25f

// ---------------- device scratch (no allocations allowed) ----------------
__device__ float g_zz[N_ROWS];
__device__ float g_ee[NE];
__device__ int   g_idx[N_ROWS];
__device__ float g_sumsq;
__device__ float g_sumw;

// ---------------- init: zero accumulators every replay ----------------
__global__ void vq_init_kernel() { g_sumsq = 0.0f; g_sumw = 0.0f; }

// ---------------- zz[n] = sum_c z[b,c,h,w]^2 ; also sum of (m==0) -------
__global__ void vq_zz_kernel(const float* __restrict__ z,
                             const float* __restrict__ m) {
    int n = blockIdx.x * blockDim.x + threadIdx.x;   // 0..32767
    int b = n >> 12;
    int r = n & 4095;
    const float* p = z + ((size_t)b * C_DIM) * HW + r;
    float s = 0.0f;
#pragma unroll 8
    for (int c = 0; c < C_DIM; c++) {
        float v = p[(size_t)c * HW];
        s = fmaf(v, v, s);
    }
    g_zz[n] = s;
    float w = (m[n] == 0.0f) ? 1.0f : 0.0f;
#pragma unroll
    for (int o = 16; o; o >>= 1) w += __shfl_xor_sync(0xffffffffu, w, o);
    if ((threadIdx.x & 31) == 0) atomicAdd(&g_sumw, w);
}

// ---------------- ee[j] = ||codebook[j]||^2 (one warp per row) ----------
__global__ void vq_ee_kernel(const float* __restrict__ cb) {
    int warp = (blockIdx.x * blockDim.x + threadIdx.x) >> 5;  // 0..8191
    int lane = threadIdx.x & 31;
    const float4* p = (const float4*)(cb + (size_t)warp * C_DIM);
    float s = 0.0f;
#pragma unroll
    for (int i = 0; i < 4; i++) {
        float4 v = p[lane + 32 * i];
        s = fmaf(v.x, v.x, fmaf(v.y, v.y, fmaf(v.z, v.z, fmaf(v.w, v.w, s))));
    }
#pragma unroll
    for (int o = 16; o; o >>= 1) s += __shfl_xor_sync(0xffffffffu, s, o);
    if (lane == 0) g_ee[warp] = s;
}

// ---------------- fused GEMM + argmin ----------------
// CTA: 128 rows, loops all 8192 codes in 128-wide tiles, K=512 in 16-chunks.
// Per-thread 8x8 micro-tile as 8x4 packed f32x2 accumulators.
__global__ void __launch_bounds__(256, 2)
vq_argmin_kernel(const float* __restrict__ z, const float* __restrict__ cb) {
    __shared__ float As[KB][TM + 4];   // [16][132] k-major
    __shared__ float Bs[KB][TN + 4];   // [16][132] k-major (transposed on load)

    const int tid = threadIdx.x;
    const int tx = tid & 15;
    const int ty = tid >> 4;
    const int row_base = blockIdx.x * TM;
    const int b = row_base >> 12;
    const int rloc = row_base & 4095;
    const float* zbase = z + ((size_t)b * C_DIM) * HW + rloc;

    // A-load mapping: 16 channels x 128 rows per chunk, float4 per thread x2
    const int a_c  = tid >> 5;          // 0..7 (then +8)
    const int a_r4 = (tid & 31) * 4;    // row within tile
    // B-load mapping: row j of codebook, 8 channels per thread x? (2 float4)
    const int b_j  = tid >> 1;          // 0..127
    const int b_q8 = (tid & 1) * 8;     // channel offset 0 or 8

    float minv[8];
    int   mini[8];
    float zzr[8];
#pragma unroll
    for (int i = 0; i < 8; i++) {
        minv[i] = __int_as_float(0x7f800000);  // +inf
        mini[i] = 0;
        zzr[i]  = g_zz[row_base + ty * 8 + i];
    }

    for (int nt = 0; nt < NE; nt += TN) {
        unsigned long long acc[8][4];
#pragma unroll
        for (int i = 0; i < 8; i++)
#pragma unroll
            for (int p = 0; p < 4; p++) acc[i][p] = 0ull;

        for (int k0 = 0; k0 < C_DIM; k0 += KB) {
            // stage A (coalesced: contiguous rows for each channel)
#pragma unroll
            for (int cc = 0; cc < 2; cc++) {
                int c = a_c + cc * 8;
                float4 v = *(const float4*)(zbase + (size_t)(k0 + c) * HW + a_r4);
                *(float4*)&As[c][a_r4] = v;
            }
            // stage B (transpose: codebook row-major -> k-major smem)
            {
                const float* p = cb + (size_t)(nt + b_j) * C_DIM + k0 + b_q8;
                float4 v0 = *(const float4*)p;
                float4 v1 = *(const float4*)(p + 4);
                Bs[b_q8 + 0][b_j] = v0.x; Bs[b_q8 + 1][b_j] = v0.y;
                Bs[b_q8 + 2][b_j] = v0.z; Bs[b_q8 + 3][b_j] = v0.w;
                Bs[b_q8 + 4][b_j] = v1.x; Bs[b_q8 + 5][b_j] = v1.y;
                Bs[b_q8 + 6][b_j] = v1.z; Bs[b_q8 + 7][b_j] = v1.w;
            }
            __syncthreads();

#pragma unroll
            for (int k = 0; k < KB; k++) {
                float4 a0 = *(const float4*)&As[k][ty * 8];
                float4 a1 = *(const float4*)&As[k][ty * 8 + 4];
                float4 b0 = *(const float4*)&Bs[k][tx * 8];
                float4 b1 = *(const float4*)&Bs[k][tx * 8 + 4];
                unsigned long long bb[4];
                asm("mov.b64 %0, {%1, %2};" : "=l"(bb[0]) : "r"(__float_as_uint(b0.x)), "r"(__float_as_uint(b0.y)));
                asm("mov.b64 %0, {%1, %2};" : "=l"(bb[1]) : "r"(__float_as_uint(b0.z)), "r"(__float_as_uint(b0.w)));
                asm("mov.b64 %0, {%1, %2};" : "=l"(bb[2]) : "r"(__float_as_uint(b1.x)), "r"(__float_as_uint(b1.y)));
                asm("mov.b64 %0, {%1, %2};" : "=l"(bb[3]) : "r"(__float_as_uint(b1.z)), "r"(__float_as_uint(b1.w)));
                float av[8] = {a0.x, a0.y, a0.z, a0.w, a1.x, a1.y, a1.z, a1.w};
#pragma unroll
                for (int i = 0; i < 8; i++) {
                    unsigned long long ap;
                    asm("mov.b64 %0, {%1, %1};" : "=l"(ap) : "r"(__float_as_uint(av[i])));
#pragma unroll
                    for (int p = 0; p < 4; p++) {
                        asm("fma.rn.f32x2 %0, %1, %2, %0;"
                            : "+l"(acc[i][p]) : "l"(ap), "l"(bb[p]));
                    }
                }
            }
            __syncthreads();
        }

        // epilogue: d = fp32(fp32(zz+ee) - 2*dot), running argmin (ascending col)
#pragma unroll
        for (int i = 0; i < 8; i++) {
#pragma unroll
            for (int p = 0; p < 4; p++) {
                unsigned int u0, u1;
                asm("mov.b64 {%0, %1}, %2;" : "=r"(u0), "=r"(u1) : "l"(acc[i][p]));
                float d0 = __uint_as_float(u0);
                float d1 = __uint_as_float(u1);
                int col0 = nt + tx * 8 + p * 2;
                float e0 = __ldg(&g_ee[col0]);
                float e1 = __ldg(&g_ee[col0 + 1]);
                float v0 = __fsub_rn(__fadd_rn(zzr[i], e0), 2.0f * d0);
                float v1 = __fsub_rn(__fadd_rn(zzr[i], e1), 2.0f * d1);
                if (v0 < minv[i]) { minv[i] = v0; mini[i] = col0; }
                if (v1 < minv[i]) { minv[i] = v1; mini[i] = col0 + 1; }
            }
        }
    }

    // combine across the 16 tx-lanes sharing each row (first-index tie-break)
#pragma unroll
    for (int i = 0; i < 8; i++) {
#pragma unroll
        for (int o = 8; o; o >>= 1) {
            float ov = __shfl_xor_sync(0xffffffffu, minv[i], o);
            int   oi = __shfl_xor_sync(0xffffffffu, mini[i], o);
            if (ov < minv[i] || (ov == minv[i] && oi < mini[i])) {
                minv[i] = ov; mini[i] = oi;
            }
        }
        if (tx == 0) g_idx[row_base + ty * 8 + i] = mini[i];
    }
}

// ---------------- gather + straight-through output + loss partials ------
__global__ void __launch_bounds__(256)
vq_output_kernel(const float* __restrict__ z, const float* __restrict__ m,
                 const float* __restrict__ cb, float* __restrict__ out) {
    __shared__ float zs[KB][TM + 4];
    const int tid = threadIdx.x;
    const int row_base = blockIdx.x * TM;
    const int b = row_base >> 12;
    const int rloc = row_base & 4095;
    const float* zbase = z + ((size_t)b * C_DIM) * HW + rloc;

    const int r  = tid >> 1;          // row within tile (0..127)
    const int h8 = (tid & 1) * 8;     // channel half offset
    const int a_c  = tid >> 5;
    const int a_r4 = (tid & 31) * 4;

    const int myidx = g_idx[row_base + r];
    const float* cbrow = cb + (size_t)myidx * C_DIM;
    float* orow = out + (size_t)(row_base + r) * C_DIM;

    float ssq = 0.0f;
    for (int k0 = 0; k0 < C_DIM; k0 += KB) {
#pragma unroll
        for (int cc = 0; cc < 2; cc++) {
            int c = a_c + cc * 8;
            *(float4*)&zs[c][a_r4] =
                *(const float4*)(zbase + (size_t)(k0 + c) * HW + a_r4);
        }
        __syncthreads();

        float4 q0 = *(const float4*)(cbrow + k0 + h8);
        float4 q1 = *(const float4*)(cbrow + k0 + h8 + 4);
        float zq[8] = {q0.x, q0.y, q0.z, q0.w, q1.x, q1.y, q1.z, q1.w};
        float o[8];
#pragma unroll
        for (int q = 0; q < 8; q++) {
            float zf = zs[h8 + q][r];
            float t = zq[q] - zf;               // z_q - z
            ssq = fmaf(t, t, ssq);
            o[q] = zf + t;                      // straight-through: z + (z_q - z)
        }
        *(float4*)(orow + k0 + h8)     = make_float4(o[0], o[1], o[2], o[3]);
        *(float4*)(orow + k0 + h8 + 4) = make_float4(o[4], o[5], o[6], o[7]);
        __syncthreads();
    }

    // combine the two channel-halves of each row, weight by mask, accumulate
    ssq += __shfl_xor_sync(0xffffffffu, ssq, 1);
    if ((tid & 1) == 0) {
        float w = (m[row_base + r] == 0.0f) ? 1.0f : 0.0f;
        if (w != 0.0f) atomicAdd(&g_sumsq, ssq);
    }
}

// ---------------- write idx (as float) and the scalar loss --------------
__global__ void vq_finalize_kernel(float* __restrict__ out) {
    int n = blockIdx.x * blockDim.x + threadIdx.x;
    if (n < N_ROWS)
        out[(size_t)N_ROWS * C_DIM + 1 + n] = (float)g_idx[n];
    if (n == 0) {
        float denom = g_sumw * (float)C_DIM;
        out[(size_t)N_ROWS * C_DIM] = (1.0f + BETA_F) * g_sumsq / denom;
    }
}

// ---------------- launch ----------------
extern "C" void kernel_launch(void* const* d_in, const int* in_sizes, int n_in,
                              void* d_out, int out_size) {
    (void)in_sizes; (void)n_in; (void)out_size;
    const float* z  = (const float*)d_in[0];
    const float* m  = (const float*)d_in[1];
    const float* cb = (const float*)d_in[2];
    float* out = (float*)d_out;

    vq_init_kernel<<<1, 1>>>();
    vq_zz_kernel<<<N_ROWS / 256, 256>>>(z, m);
    vq_ee_kernel<<<NE * 32 / 256, 256>>>(cb);
    vq_argmin_kernel<<<N_ROWS / TM, 256>>>(z, cb);
    vq_output_kernel<<<N_ROWS / TM, 256>>>(z, m, cb, out);
    vq_finalize_kernel<<<N_ROWS / 256, 256>>>(out);
}

// round 3
// speedup vs baseline: 1.0288x; 1.0288x over previous
#include <cuda_runtime.h>

#define N_ROWS 32768
#define C_DIM  512
#define NE     8192
#define HW     4096
#define TM     256          // rows per CTA (argmin)
#define TNT    64           // codebook cols per tile
#define KB     16           // k-chunk
#define SPLITS 8
#define TILES_PER_SPLIT (NE / TNT / SPLITS)   // 16
#define OTM    128          // rows per CTA (output kernel)
#define BETA_F 0.25f

// ---------------- device scratch ----------------
__device__ float g_zz[N_ROWS];
__device__ float g_ee[NE];
__device__ unsigned long long g_best[N_ROWS];   // (dist_bits<<32)|idx
__device__ float g_sumsq;
__device__ float g_sumw;

// ---------------- helpers ----------------
__device__ __forceinline__ unsigned long long dup_f32(float x) {
    unsigned long long r;
    asm("mov.b64 %0, {%1, %1};" : "=l"(r) : "r"(__float_as_uint(x)));
    return r;
}
__device__ __forceinline__ void lds_v2u64(unsigned long long &x, unsigned long long &y,
                                          unsigned addr) {
    asm volatile("ld.shared.v2.b64 {%0,%1},[%2];" : "=l"(x), "=l"(y) : "r"(addr));
}
__device__ __forceinline__ void ffma2(unsigned long long &acc, unsigned long long a,
                                      unsigned long long b) {
    asm("fma.rn.f32x2 %0,%1,%2,%0;" : "+l"(acc) : "l"(a), "l"(b));
}
__device__ __forceinline__ unsigned swz(unsigned g) { return g ^ ((g >> 3) & 1u); }

// ---------------- init (every replay) ----------------
__global__ void vq_init_kernel() {
    int n = blockIdx.x * blockDim.x + threadIdx.x;
    if (n < N_ROWS) g_best[n] = ~0ull;
    if (n == 0) { g_sumsq = 0.0f; g_sumw = 0.0f; }
}

// ---------------- zz[n] = sum_c z^2 ; sum of (m==0) ----------------
__global__ void vq_zz_kernel(const float* __restrict__ z,
                             const float* __restrict__ m) {
    int n = blockIdx.x * blockDim.x + threadIdx.x;
    int b = n >> 12;
    int r = n & 4095;
    const float* p = z + ((size_t)b * C_DIM) * HW + r;
    float s = 0.0f;
#pragma unroll 8
    for (int c = 0; c < C_DIM; c++) {
        float v = p[(size_t)c * HW];
        s = fmaf(v, v, s);
    }
    g_zz[n] = s;
    float w = (m[n] == 0.0f) ? 1.0f : 0.0f;
#pragma unroll
    for (int o = 16; o; o >>= 1) w += __shfl_xor_sync(0xffffffffu, w, o);
    if ((threadIdx.x & 31) == 0) atomicAdd(&g_sumw, w);
}

// ---------------- ee[j] = ||codebook[j]||^2 ----------------
__global__ void vq_ee_kernel(const float* __restrict__ cb) {
    int warp = (blockIdx.x * blockDim.x + threadIdx.x) >> 5;
    int lane = threadIdx.x & 31;
    const float4* p = (const float4*)(cb + (size_t)warp * C_DIM);
    float s = 0.0f;
#pragma unroll
    for (int i = 0; i < 4; i++) {
        float4 v = p[lane + 32 * i];
        s = fmaf(v.x, v.x, fmaf(v.y, v.y, fmaf(v.z, v.z, fmaf(v.w, v.w, s))));
    }
#pragma unroll
    for (int o = 16; o; o >>= 1) s += __shfl_xor_sync(0xffffffffu, s, o);
    if (lane == 0) g_ee[warp] = s;
}

// ---------------- fused GEMM + argmin ----------------
// CTA = 256 rows x (1024-code split). Warp = 32 lanes x 8 contiguous rows,
// all lanes share the warp's 8 columns (B reads are warp-uniform broadcast).
// A smem XOR-swizzled (conflict-free LDS.128); B smem stored as {b,b} u64
// pairs so fma.rn.f32x2 operands come straight from ld.shared.v2.b64.
__global__ void __launch_bounds__(256, 2)
vq_argmin_kernel(const float* __restrict__ z, const float* __restrict__ cb) {
    __shared__ __align__(16) char smbuf[24576];
    float* As = (float*)smbuf;                                     // 16KB: [KB][256] swizzled
    unsigned long long* Bs = (unsigned long long*)(smbuf + 16384); // 8KB:  [KB][64] dup pairs
    unsigned long long (*sRed)[TM] = (unsigned long long(*)[TM])smbuf; // alias for final reduce

    const int tid  = threadIdx.x;
    const int warp = tid >> 5;        // 0..7 = column group
    const int lane = tid & 31;        // covers rows 8*lane .. 8*lane+7

    const int rb   = (blockIdx.x & 127) * TM;
    const int nt0  = (blockIdx.x >> 7) * (TILES_PER_SPLIT * TNT);
    const int b    = rb >> 12;
    const int rloc = rb & 4095;
    const float* zbase = z + ((size_t)b * C_DIM) * HW + rloc;

    // A staging mapping: channel c0 (+8), rows rr..rr+7 (two float4)
    const int a_c0 = tid >> 5;
    const int a_rr = (tid & 31) * 8;
    const unsigned a_so0 = swz(2u * (tid & 31)) * 16u;
    const unsigned a_so1 = swz(2u * (tid & 31) + 1u) * 16u;
    // B staging mapping: code cB, k-quad kq
    const int b_cB = tid >> 2;
    const int b_kq = tid & 3;

    const unsigned AsBase = (unsigned)__cvta_generic_to_shared(As);
    const unsigned BsBase = (unsigned)__cvta_generic_to_shared(Bs);
    const unsigned aAddr0 = AsBase + swz(2u * lane) * 16u;       // rows 8l..8l+3
    const unsigned aAddr1 = AsBase + swz(2u * lane + 1u) * 16u;  // rows 8l+4..8l+7
    const unsigned bAddr  = BsBase + warp * 64u;                 // this warp's 8 cols

    float zzr[8];
#pragma unroll
    for (int i = 0; i < 8; i++) zzr[i] = g_zz[rb + 8 * lane + i];

    unsigned long long best[8];
#pragma unroll
    for (int i = 0; i < 8; i++) best[i] = ~0ull;

    for (int t = 0; t < TILES_PER_SPLIT; t++) {
        const int nt = nt0 + t * TNT;

        unsigned long long acc[8][4];   // [col c][row-pair p]
#pragma unroll
        for (int c = 0; c < 8; c++)
#pragma unroll
            for (int p = 0; p < 4; p++) acc[c][p] = 0ull;

        for (int k0 = 0; k0 < C_DIM; k0 += KB) {
            // ---- stage A (coalesced LDG, swizzled STS) ----
#pragma unroll
            for (int cc = 0; cc < 2; cc++) {
                int c = a_c0 + 8 * cc;
                const float4* gp = (const float4*)(zbase + (size_t)(k0 + c) * HW + a_rr);
                float4 v0 = gp[0];
                float4 v1 = gp[1];
                *(float4*)((char*)As + c * 1024 + a_so0) = v0;
                *(float4*)((char*)As + c * 1024 + a_so1) = v1;
            }
            // ---- stage B (duplicate each value into a {b,b} pair) ----
            {
                const float4 v = *(const float4*)(cb + (size_t)(nt + b_cB) * C_DIM + k0 + b_kq * 4);
                unsigned long long* bp = Bs + (b_kq * 4) * TNT + b_cB;
                bp[0 * TNT] = dup_f32(v.x);
                bp[1 * TNT] = dup_f32(v.y);
                bp[2 * TNT] = dup_f32(v.z);
                bp[3 * TNT] = dup_f32(v.w);
            }
            __syncthreads();

#pragma unroll
            for (int k = 0; k < KB; k++) {
                unsigned long long a0, a1, a2, a3;
                lds_v2u64(a0, a1, aAddr0 + (unsigned)k * 1024u);
                lds_v2u64(a2, a3, aAddr1 + (unsigned)k * 1024u);
                unsigned long long bv[8];
                lds_v2u64(bv[0], bv[1], bAddr + (unsigned)k * 512u + 0u);
                lds_v2u64(bv[2], bv[3], bAddr + (unsigned)k * 512u + 16u);
                lds_v2u64(bv[4], bv[5], bAddr + (unsigned)k * 512u + 32u);
                lds_v2u64(bv[6], bv[7], bAddr + (unsigned)k * 512u + 48u);
#pragma unroll
                for (int c = 0; c < 8; c++) {
                    ffma2(acc[c][0], a0, bv[c]);
                    ffma2(acc[c][1], a1, bv[c]);
                    ffma2(acc[c][2], a2, bv[c]);
                    ffma2(acc[c][3], a3, bv[c]);
                }
            }
            __syncthreads();
        }

        // ---- epilogue: d = fp32(fp32(zz+ee) - 2*dot), packed running min ----
#pragma unroll
        for (int c = 0; c < 8; c++) {
            const int col = nt + warp * 8 + c;
            const float ee = __ldg(&g_ee[col]);
#pragma unroll
            for (int p = 0; p < 4; p++) {
                unsigned u0, u1;
                asm("mov.b64 {%0,%1},%2;" : "=r"(u0), "=r"(u1) : "l"(acc[c][p]));
                float d0 = __uint_as_float(u0);   // row 8l+2p
                float d1 = __uint_as_float(u1);   // row 8l+2p+1
                float v0 = __fsub_rn(__fadd_rn(zzr[2 * p],     ee), 2.0f * d0);
                float v1 = __fsub_rn(__fadd_rn(zzr[2 * p + 1], ee), 2.0f * d1);
                unsigned long long pv0 = ((unsigned long long)__float_as_uint(v0) << 32) | (unsigned)col;
                unsigned long long pv1 = ((unsigned long long)__float_as_uint(v1) << 32) | (unsigned)col;
                if (pv0 < best[2 * p])     best[2 * p]     = pv0;
                if (pv1 < best[2 * p + 1]) best[2 * p + 1] = pv1;
            }
        }
    }

    // ---- cross-warp reduce (each row appears in all 8 warps) ----
    __syncthreads();   // done with As/Bs; safe to alias sRed
#pragma unroll
    for (int i = 0; i < 8; i++) sRed[warp][8 * lane + i] = best[i];
    __syncthreads();
    {
        unsigned long long m = sRed[0][tid];
#pragma unroll
        for (int w = 1; w < 8; w++) {
            unsigned long long v = sRed[w][tid];
            if (v < m) m = v;
        }
        atomicMin(&g_best[rb + tid], m);
    }
}

// ---------------- gather + straight-through output + loss partials ------
__global__ void __launch_bounds__(256)
vq_output_kernel(const float* __restrict__ z, const float* __restrict__ m,
                 const float* __restrict__ cb, float* __restrict__ out) {
    __shared__ float zs[KB][OTM + 4];
    const int tid = threadIdx.x;
    const int row_base = blockIdx.x * OTM;
    const int b = row_base >> 12;
    const int rloc = row_base & 4095;
    const float* zbase = z + ((size_t)b * C_DIM) * HW + rloc;

    const int r  = tid >> 1;
    const int h8 = (tid & 1) * 8;
    const int a_c  = tid >> 5;
    const int a_r4 = (tid & 31) * 4;

    const int myidx = (int)(g_best[row_base + r] & 0xffffffffu);
    const float* cbrow = cb + (size_t)myidx * C_DIM;
    float* orow = out + (size_t)(row_base + r) * C_DIM;

    float ssq = 0.0f;
    for (int k0 = 0; k0 < C_DIM; k0 += KB) {
#pragma unroll
        for (int cc = 0; cc < 2; cc++) {
            int c = a_c + cc * 8;
            *(float4*)&zs[c][a_r4] =
                *(const float4*)(zbase + (size_t)(k0 + c) * HW + a_r4);
        }
        __syncthreads();

        float4 q0 = *(const float4*)(cbrow + k0 + h8);
        float4 q1 = *(const float4*)(cbrow + k0 + h8 + 4);
        float zq[8] = {q0.x, q0.y, q0.z, q0.w, q1.x, q1.y, q1.z, q1.w};
        float o[8];
#pragma unroll
        for (int q = 0; q < 8; q++) {
            float zf = zs[h8 + q][r];
            float t = zq[q] - zf;
            ssq = fmaf(t, t, ssq);
            o[q] = zf + t;
        }
        *(float4*)(orow + k0 + h8)     = make_float4(o[0], o[1], o[2], o[3]);
        *(float4*)(orow + k0 + h8 + 4) = make_float4(o[4], o[5], o[6], o[7]);
        __syncthreads();
    }

    ssq += __shfl_xor_sync(0xffffffffu, ssq, 1);
    if ((tid & 1) == 0) {
        float w = (m[row_base + r] == 0.0f) ? 1.0f : 0.0f;
        if (w != 0.0f) atomicAdd(&g_sumsq, ssq);
    }
}

// ---------------- write idx (as float) and the scalar loss --------------
__global__ void vq_finalize_kernel(float* __restrict__ out) {
    int n = blockIdx.x * blockDim.x + threadIdx.x;
    if (n < N_ROWS)
        out[(size_t)N_ROWS * C_DIM + 1 + n] = (float)(int)(g_best[n] & 0xffffffffu);
    if (n == 0) {
        float denom = g_sumw * (float)C_DIM;
        out[(size_t)N_ROWS * C_DIM] = (1.0f + BETA_F) * g_sumsq / denom;
    }
}

// ---------------- launch ----------------
extern "C" void kernel_launch(void* const* d_in, const int* in_sizes, int n_in,
                              void* d_out, int out_size) {
    (void)in_sizes; (void)n_in; (void)out_size;
    const float* z  = (const float*)d_in[0];
    const float* m  = (const float*)d_in[1];
    const float* cb = (const float*)d_in[2];
    float* out = (float*)d_out;

    vq_init_kernel<<<N_ROWS / 256, 256>>>();
    vq_zz_kernel<<<N_ROWS / 256, 256>>>(z, m);
    vq_ee_kernel<<<NE * 32 / 256, 256>>>(cb);
    vq_argmin_kernel<<<128 * SPLITS, 256>>>(z, cb);
    vq_output_kernel<<<N_ROWS / OTM, 256>>>(z, m, cb, out);
    vq_finalize_kernel<<<N_ROWS / 256, 256>>>(out);
}

// round 6
// speedup vs baseline: 3.0327x; 2.9477x over previous
#include <cuda_runtime.h>
#include <cuda_bf16.h>

#define N_ROWS 32768
#define C_DIM  512
#define NE     8192
#define HW     4096
#define BETA_F 0.25f

// GEMM tiling
#define MT 128
#define NT 128
#define KC 64
#define NCHUNK (C_DIM / KC)     // 8
#define NBLK   (NE / NT)        // 64
#define MBLK   (N_ROWS / MT)    // 256
#define OTM 128
#define KB  16

// smem: 2 stages x (Ah,Am,Bh,Bm each 128x64 bf16 = 16KB) = 131072
#define STAGE_BYTES 65536u
#define TILE_BYTES  16384u
#define SMEM_TOTAL  131072

// ---------------- device scratch ----------------
__device__ float g_zz[N_ROWS];
__device__ float g_ee[NE];
__device__ unsigned long long g_best[N_ROWS];
__device__ float g_sumsq;
__device__ float g_sumw;
__device__ __nv_bfloat16 g_Ah[(size_t)N_ROWS * C_DIM];
__device__ __nv_bfloat16 g_Am[(size_t)N_ROWS * C_DIM];
__device__ __nv_bfloat16 g_Bh[(size_t)NE * C_DIM];
__device__ __nv_bfloat16 g_Bm[(size_t)NE * C_DIM];

// ---------------- ptx helpers (compute_103-baseline only) ----------------
__device__ __forceinline__ void cpa16(unsigned dst, const void* src) {
    asm volatile("cp.async.cg.shared.global [%0], [%1], 16;" :: "r"(dst), "l"(src));
}
__device__ __forceinline__ void ldsm4(unsigned &r0, unsigned &r1, unsigned &r2,
                                      unsigned &r3, unsigned addr) {
    asm volatile("ldmatrix.sync.aligned.m8n8.x4.shared.b16 {%0,%1,%2,%3},[%4];"
                 : "=r"(r0), "=r"(r1), "=r"(r2), "=r"(r3) : "r"(addr));
}
#define MMA_BF16(d, a, b) \
    asm volatile("mma.sync.aligned.m16n8k16.row.col.f32.bf16.bf16.f32 " \
        "{%0,%1,%2,%3},{%4,%5,%6,%7},{%8,%9},{%0,%1,%2,%3};" \
        : "+f"((d)[0]), "+f"((d)[1]), "+f"((d)[2]), "+f"((d)[3]) \
        : "r"((a)[0]), "r"((a)[1]), "r"((a)[2]), "r"((a)[3]), \
          "r"((b)[0]), "r"((b)[1]))

// ---------------- init (every replay) ----------------
__global__ void vq_init_kernel() {
    int n = blockIdx.x * blockDim.x + threadIdx.x;
    if (n < N_ROWS) g_best[n] = ~0ull;
    if (n == 0) { g_sumsq = 0.0f; g_sumw = 0.0f; }
}

// ---------------- zz[n] = sum_c z^2 ; sum of (m==0) ----------------
__global__ void vq_zz_kernel(const float* __restrict__ z,
                             const float* __restrict__ m) {
    int n = blockIdx.x * blockDim.x + threadIdx.x;
    int b = n >> 12;
    int r = n & 4095;
    const float* p = z + ((size_t)b * C_DIM) * HW + r;
    float s = 0.0f;
#pragma unroll 8
    for (int c = 0; c < C_DIM; c++) {
        float v = p[(size_t)c * HW];
        s = fmaf(v, v, s);
    }
    g_zz[n] = s;
    float w = (m[n] == 0.0f) ? 1.0f : 0.0f;
#pragma unroll
    for (int o = 16; o; o >>= 1) w += __shfl_xor_sync(0xffffffffu, w, o);
    if ((threadIdx.x & 31) == 0) atomicAdd(&g_sumw, w);
}

// ---------------- ee[j] = ||codebook[j]||^2 ----------------
__global__ void vq_ee_kernel(const float* __restrict__ cb) {
    int warp = (blockIdx.x * blockDim.x + threadIdx.x) >> 5;
    int lane = threadIdx.x & 31;
    const float4* p = (const float4*)(cb + (size_t)warp * C_DIM);
    float s = 0.0f;
#pragma unroll
    for (int i = 0; i < 4; i++) {
        float4 v = p[lane + 32 * i];
        s = fmaf(v.x, v.x, fmaf(v.y, v.y, fmaf(v.z, v.z, fmaf(v.w, v.w, s))));
    }
#pragma unroll
    for (int o = 16; o; o >>= 1) s += __shfl_xor_sync(0xffffffffu, s, o);
    if (lane == 0) g_ee[warp] = s;
}

// ---------------- z: NCHW -> [N,C] bf16 split (h + m) -------------------
__global__ void vq_zsplit_kernel(const float* __restrict__ z) {
    __shared__ float t[64][65];
    int bid = blockIdx.x;
    int hw0 = (bid & 63) * 64;
    int c0  = ((bid >> 6) & 7) * 64;
    int b   = bid >> 9;
    int tid = threadIdx.x;
    int q = tid >> 6;
    int l = tid & 63;
    const float* zp = z + ((size_t)b * C_DIM + c0) * HW + hw0;
#pragma unroll
    for (int s = 0; s < 16; s++) {
        int c = s * 4 + q;
        t[c][l] = zp[(size_t)c * HW + l];
    }
    __syncthreads();
    size_t rowbase = (size_t)b * HW + hw0;
#pragma unroll
    for (int s = 0; s < 16; s++) {
        int n = s * 4 + q;
        float a = t[l][n];
        __nv_bfloat16 h = __float2bfloat16(a);
        float r = a - __bfloat162float(h);
        size_t o = (rowbase + n) * C_DIM + c0 + l;
        g_Ah[o] = h;
        g_Am[o] = __float2bfloat16(r);
    }
}

// ---------------- codebook bf16 split ----------------
__global__ void vq_cbsplit_kernel(const float* __restrict__ cb) {
    int i = blockIdx.x * 256 + threadIdx.x;
    float a = cb[i];
    __nv_bfloat16 h = __float2bfloat16(a);
    float r = a - __bfloat162float(h);
    g_Bh[i] = h;
    g_Bm[i] = __float2bfloat16(r);
}

// ---------------- HMMA split-GEMM + fused argmin ----------------
// CTA tile 128x128, warp grid 2(m)x4(n), warp tile 64x32.
// D += Ah*Bh + Ah*Bm + Am*Bh (fp32 acc). cp.async 2-stage pipeline,
// XOR-swizzled smem, ldmatrix operands.
__global__ void __launch_bounds__(256, 1)
vq_mma_kernel() {
    extern __shared__ __align__(128) char sm[];
    const unsigned smb = (unsigned)__cvta_generic_to_shared(sm);

    const int tid  = threadIdx.x;
    const int lane = tid & 31;
    const int wid  = tid >> 5;
    const int wm   = wid >> 2;        // 0..1
    const int wn   = wid & 3;         // 0..3
    const int mblk = blockIdx.x >> 6;
    const int nblk = blockIdx.x & 63;

    const __nv_bfloat16* Ahg = g_Ah + (size_t)(mblk * MT) * C_DIM;
    const __nv_bfloat16* Amg = g_Am + (size_t)(mblk * MT) * C_DIM;
    const __nv_bfloat16* Bhg = g_Bh + (size_t)(nblk * NT) * C_DIM;
    const __nv_bfloat16* Bmg = g_Bm + (size_t)(nblk * NT) * C_DIM;

    // swizzle: 16B-column byte ^= (row&7)<<4 ; identical for A and B tiles
    const unsigned axor  = (unsigned)(lane & 7) << 4;
    const unsigned aoff  = (unsigned)(((lane & 7) + ((lane >> 3) & 1) * 8) * 128);
    const unsigned acolb = (unsigned)(((lane >> 4) & 1) * 16);
    const unsigned boff  = (unsigned)(((lane & 7) + ((lane >> 4) & 1) * 8) * 128);
    const unsigned bcolb = (unsigned)(((lane >> 3) & 1) * 16);

    float acc[4][4][4];
#pragma unroll
    for (int mt = 0; mt < 4; mt++)
#pragma unroll
        for (int nf = 0; nf < 4; nf++)
#pragma unroll
            for (int r = 0; r < 4; r++) acc[mt][nf][r] = 0.0f;

    auto load_stage = [&](int st, int k0) {
        const unsigned sb0 = smb + (unsigned)st * STAGE_BYTES;
#pragma unroll
        for (int i = 0; i < 4; i++) {
            int g = tid + 256 * i;
            int row = g >> 3;
            int c = g & 7;
            unsigned off = (unsigned)(row * 128) +
                           (((unsigned)(c * 16)) ^ ((unsigned)(row & 7) << 4));
            const size_t so = (size_t)row * C_DIM + k0 + c * 8;
            cpa16(sb0 + 0u * TILE_BYTES + off, Ahg + so);
            cpa16(sb0 + 1u * TILE_BYTES + off, Amg + so);
            cpa16(sb0 + 2u * TILE_BYTES + off, Bhg + so);
            cpa16(sb0 + 3u * TILE_BYTES + off, Bmg + so);
        }
        asm volatile("cp.async.commit_group;" ::: "memory");
    };

    load_stage(0, 0);

    for (int c = 0; c < NCHUNK; c++) {
        const int st = c & 1;
        if (c + 1 < NCHUNK) {
            load_stage(st ^ 1, (c + 1) * KC);
            asm volatile("cp.async.wait_group 1;" ::: "memory");
        } else {
            asm volatile("cp.async.wait_group 0;" ::: "memory");
        }
        __syncthreads();

#pragma unroll
        for (int p = 0; p < 3; p++) {
            const unsigned sa = smb + (unsigned)st * STAGE_BYTES + (p == 2 ? TILE_BYTES : 0u);
            const unsigned sb = smb + (unsigned)st * STAGE_BYTES + 2u * TILE_BYTES
                                + (p == 1 ? TILE_BYTES : 0u);
#pragma unroll
            for (int ks = 0; ks < 4; ks++) {
                unsigned af[4][4];
#pragma unroll
                for (int mt = 0; mt < 4; mt++) {
                    unsigned addr = sa + (unsigned)((wm * 64 + mt * 16) * 128) + aoff
                                    + (((unsigned)(ks * 32) + acolb) ^ axor);
                    ldsm4(af[mt][0], af[mt][1], af[mt][2], af[mt][3], addr);
                }
                unsigned bf[4][2];
#pragma unroll
                for (int g2 = 0; g2 < 2; g2++) {
                    unsigned addr = sb + (unsigned)((wn * 32 + g2 * 16) * 128) + boff
                                    + (((unsigned)(ks * 32) + bcolb) ^ axor);
                    ldsm4(bf[g2 * 2][0], bf[g2 * 2][1],
                          bf[g2 * 2 + 1][0], bf[g2 * 2 + 1][1], addr);
                }
#pragma unroll
                for (int mt = 0; mt < 4; mt++)
#pragma unroll
                    for (int nf = 0; nf < 4; nf++)
                        MMA_BF16(acc[mt][nf], af[mt], bf[nf]);
            }
        }
        __syncthreads();
    }

    // ---- epilogue: exact v = fp32(fp32(zz+ee) - 2*dot), packed min ----
    unsigned long long* sRed = (unsigned long long*)sm;   // [4][128]
#pragma unroll
    for (int mt = 0; mt < 4; mt++) {
#pragma unroll
        for (int rh = 0; rh < 2; rh++) {
            const int mloc = wm * 64 + mt * 16 + (lane >> 2) + rh * 8;
            const float zz = g_zz[mblk * MT + mloc];
            unsigned long long best = ~0ull;
#pragma unroll
            for (int nf = 0; nf < 4; nf++) {
#pragma unroll
                for (int q = 0; q < 2; q++) {
                    const int n = nblk * NT + wn * 32 + nf * 8 + (lane & 3) * 2 + q;
                    float d = acc[mt][nf][rh * 2 + q];
                    float v = __fsub_rn(__fadd_rn(zz, __ldg(&g_ee[n])), 2.0f * d);
                    unsigned long long pv =
                        ((unsigned long long)__float_as_uint(v) << 32) | (unsigned)n;
                    if (pv < best) best = pv;
                }
            }
#pragma unroll
            for (int o = 1; o <= 2; o <<= 1) {
                unsigned long long ov = __shfl_xor_sync(0xffffffffu, best, o);
                if (ov < best) best = ov;
            }
            if ((lane & 3) == 0) sRed[wn * 128 + mloc] = best;
        }
    }
    __syncthreads();
    if (tid < 128) {
        unsigned long long b = sRed[tid];
#pragma unroll
        for (int w = 1; w < 4; w++) {
            unsigned long long v = sRed[w * 128 + tid];
            if (v < b) b = v;
        }
        atomicMin(&g_best[mblk * MT + tid], b);
    }
}

// ---------------- gather + straight-through output + loss partials ------
__global__ void __launch_bounds__(256)
vq_output_kernel(const float* __restrict__ z, const float* __restrict__ m,
                 const float* __restrict__ cb, float* __restrict__ out) {
    __shared__ float zs[KB][OTM + 4];
    const int tid = threadIdx.x;
    const int row_base = blockIdx.x * OTM;
    const int b = row_base >> 12;
    const int rloc = row_base & 4095;
    const float* zbase = z + ((size_t)b * C_DIM) * HW + rloc;

    const int r  = tid >> 1;
    const int h8 = (tid & 1) * 8;
    const int a_c  = tid >> 5;
    const int a_r4 = (tid & 31) * 4;

    const int myidx = (int)(g_best[row_base + r] & 0xffffffffu);
    const float* cbrow = cb + (size_t)myidx * C_DIM;
    float* orow = out + (size_t)(row_base + r) * C_DIM;

    float ssq = 0.0f;
    for (int k0 = 0; k0 < C_DIM; k0 += KB) {
#pragma unroll
        for (int cc = 0; cc < 2; cc++) {
            int c = a_c + cc * 8;
            *(float4*)&zs[c][a_r4] =
                *(const float4*)(zbase + (size_t)(k0 + c) * HW + a_r4);
        }
        __syncthreads();

        float4 q0 = *(const float4*)(cbrow + k0 + h8);
        float4 q1 = *(const float4*)(cbrow + k0 + h8 + 4);
        float zq[8] = {q0.x, q0.y, q0.z, q0.w, q1.x, q1.y, q1.z, q1.w};
        float o[8];
#pragma unroll
        for (int q = 0; q < 8; q++) {
            float zf = zs[h8 + q][r];
            float t = zq[q] - zf;
            ssq = fmaf(t, t, ssq);
            o[q] = zf + t;
        }
        *(float4*)(orow + k0 + h8)     = make_float4(o[0], o[1], o[2], o[3]);
        *(float4*)(orow + k0 + h8 + 4) = make_float4(o[4], o[5], o[6], o[7]);
        __syncthreads();
    }

    ssq += __shfl_xor_sync(0xffffffffu, ssq, 1);
    if ((tid & 1) == 0) {
        float w = (m[row_base + r] == 0.0f) ? 1.0f : 0.0f;
        if (w != 0.0f) atomicAdd(&g_sumsq, ssq);
    }
}

// ---------------- write idx (as float) and the scalar loss --------------
__global__ void vq_finalize_kernel(float* __restrict__ out) {
    int n = blockIdx.x * blockDim.x + threadIdx.x;
    if (n < N_ROWS)
        out[(size_t)N_ROWS * C_DIM + 1 + n] = (float)(int)(g_best[n] & 0xffffffffu);
    if (n == 0) {
        float denom = g_sumw * (float)C_DIM;
        out[(size_t)N_ROWS * C_DIM] = (1.0f + BETA_F) * g_sumsq / denom;
    }
}

// ---------------- launch ----------------
extern "C" void kernel_launch(void* const* d_in, const int* in_sizes, int n_in,
                              void* d_out, int out_size) {
    (void)in_sizes; (void)n_in; (void)out_size;
    const float* z  = (const float*)d_in[0];
    const float* m  = (const float*)d_in[1];
    const float* cb = (const float*)d_in[2];
    float* out = (float*)d_out;

    cudaFuncSetAttribute(vq_mma_kernel,
                         cudaFuncAttributeMaxDynamicSharedMemorySize, SMEM_TOTAL);

    vq_init_kernel<<<N_ROWS / 256, 256>>>();
    vq_zz_kernel<<<N_ROWS / 256, 256>>>(z, m);
    vq_ee_kernel<<<NE * 32 / 256, 256>>>(cb);
    vq_zsplit_kernel<<<4096, 256>>>(z);
    vq_cbsplit_kernel<<<NE * C_DIM / 256, 256>>>(cb);
    vq_mma_kernel<<<MBLK * NBLK, 256, SMEM_TOTAL>>>();
    vq_output_kernel<<<N_ROWS / OTM, 256>>>(z, m, cb, out);
    vq_finalize_kernel<<<N_ROWS / 256, 256>>>(out);
}

// round 7
// speedup vs baseline: 5.5414x; 1.8272x over previous
#include <cuda_runtime.h>
#include <cuda_bf16.h>

#define N_ROWS 32768
#define C_DIM  512
#define NE     8192
#define HW     4096
#define BETA_F 0.25f

// GEMM tiling (single bf16 pass)
#define MT 128
#define NT 128
#define KC 64
#define NCHUNK (C_DIM / KC)     // 8
#define NBLK   (NE / NT)        // 64
#define MBLK   (N_ROWS / MT)    // 256

#define STAGE_BYTES 32768u      // Ah 16KB + Bh 16KB
#define TILE_BYTES  16384u
#define SMEM_TOTAL  65536

// ---------------- device scratch ----------------
__device__ float g_zz[N_ROWS];
__device__ float g_eps[N_ROWS];
__device__ float g_ee[NE];
__device__ unsigned g_amin[N_ROWS];              // min sortable key per row
__device__ unsigned long long g_best[N_ROWS];    // exact (v_bits<<32)|idx
__device__ float g_sumsq;
__device__ float g_sumw;
__device__ __nv_bfloat16 g_Ah[(size_t)N_ROWS * C_DIM];
__device__ __nv_bfloat16 g_Bh[(size_t)NE * C_DIM];
__device__ float g_zt[(size_t)N_ROWS * C_DIM];   // z transposed to [N,C] fp32
__device__ unsigned short g_S[(size_t)N_ROWS * NE];  // 512MB key matrix

// ---------------- helpers ----------------
__device__ __forceinline__ void cpa16(unsigned dst, const void* src) {
    asm volatile("cp.async.cg.shared.global [%0], [%1], 16;" :: "r"(dst), "l"(src));
}
__device__ __forceinline__ void ldsm4(unsigned &r0, unsigned &r1, unsigned &r2,
                                      unsigned &r3, unsigned addr) {
    asm volatile("ldmatrix.sync.aligned.m8n8.x4.shared.b16 {%0,%1,%2,%3},[%4];"
                 : "=r"(r0), "=r"(r1), "=r"(r2), "=r"(r3) : "r"(addr));
}
#define MMA_BF16(d, a, b) \
    asm volatile("mma.sync.aligned.m16n8k16.row.col.f32.bf16.bf16.f32 " \
        "{%0,%1,%2,%3},{%4,%5,%6,%7},{%8,%9},{%0,%1,%2,%3};" \
        : "+f"((d)[0]), "+f"((d)[1]), "+f"((d)[2]), "+f"((d)[3]) \
        : "r"((a)[0]), "r"((a)[1]), "r"((a)[2]), "r"((a)[3]), \
          "r"((b)[0]), "r"((b)[1]))

// monotone 16-bit key from float (sortable as unsigned)
__device__ __forceinline__ unsigned skey(float s) {
    unsigned b = __float_as_uint(s);
    b ^= (b & 0x80000000u) ? 0xFFFFFFFFu : 0x80000000u;
    return b >> 16;
}
__device__ __forceinline__ float skey_inv(unsigned v) {   // v = full 32-bit pattern
    return (v & 0x80000000u) ? __uint_as_float(v ^ 0x80000000u)
                             : __uint_as_float(~v);
}

// ---------------- init (every replay) ----------------
__global__ void vq_init_kernel() {
    int n = blockIdx.x * blockDim.x + threadIdx.x;
    if (n < N_ROWS) g_amin[n] = 0xFFFFFFFFu;
    if (n == 0) { g_sumsq = 0.0f; g_sumw = 0.0f; }
}

// ---------------- zz, Σ|z| -> eps, mask sum ----------------
__global__ void vq_zz_kernel(const float* __restrict__ z,
                             const float* __restrict__ m) {
    int n = blockIdx.x * blockDim.x + threadIdx.x;
    int b = n >> 12;
    int r = n & 4095;
    const float* p = z + ((size_t)b * C_DIM) * HW + r;
    float s = 0.0f, sa = 0.0f;
#pragma unroll 8
    for (int c = 0; c < C_DIM; c++) {
        float v = p[(size_t)c * HW];
        s = fmaf(v, v, s);
        sa += fabsf(v);
    }
    g_zz[n] = s;
    g_eps[n] = fmaf(2.0e-6f, sa, 3.0e-4f);   // bound on |s_approx - (v_exact - zz)|
    float w = (m[n] == 0.0f) ? 1.0f : 0.0f;
#pragma unroll
    for (int o = 16; o; o >>= 1) w += __shfl_xor_sync(0xffffffffu, w, o);
    if ((threadIdx.x & 31) == 0) atomicAdd(&g_sumw, w);
}

// ---------------- ee[j] = ||codebook[j]||^2 ----------------
__global__ void vq_ee_kernel(const float* __restrict__ cb) {
    int warp = (blockIdx.x * blockDim.x + threadIdx.x) >> 5;
    int lane = threadIdx.x & 31;
    const float4* p = (const float4*)(cb + (size_t)warp * C_DIM);
    float s = 0.0f;
#pragma unroll
    for (int i = 0; i < 4; i++) {
        float4 v = p[lane + 32 * i];
        s = fmaf(v.x, v.x, fmaf(v.y, v.y, fmaf(v.z, v.z, fmaf(v.w, v.w, s))));
    }
#pragma unroll
    for (int o = 16; o; o >>= 1) s += __shfl_xor_sync(0xffffffffu, s, o);
    if (lane == 0) g_ee[warp] = s;
}

// ---------------- z: NCHW -> [N,C] (fp32 zt + bf16 Ah) ----------------
__global__ void vq_zsplit_kernel(const float* __restrict__ z) {
    __shared__ float t[64][65];
    int bid = blockIdx.x;
    int hw0 = (bid & 63) * 64;
    int c0  = ((bid >> 6) & 7) * 64;
    int b   = bid >> 9;
    int tid = threadIdx.x;
    int q = tid >> 6;
    int l = tid & 63;
    const float* zp = z + ((size_t)b * C_DIM + c0) * HW + hw0;
#pragma unroll
    for (int s = 0; s < 16; s++) {
        int c = s * 4 + q;
        t[c][l] = zp[(size_t)c * HW + l];
    }
    __syncthreads();
    size_t rowbase = (size_t)b * HW + hw0;
#pragma unroll
    for (int s = 0; s < 16; s++) {
        int n = s * 4 + q;
        float a = t[l][n];
        size_t o = (rowbase + n) * C_DIM + c0 + l;
        g_zt[o] = a;
        g_Ah[o] = __float2bfloat16(a);
    }
}

// ---------------- codebook -> bf16 ----------------
__global__ void vq_cbsplit_kernel(const float* __restrict__ cb) {
    int i = blockIdx.x * 256 + threadIdx.x;
    g_Bh[i] = __float2bfloat16(cb[i]);
}

// ---------------- single-pass HMMA GEMM: keys + per-row min ----------------
__global__ void __launch_bounds__(256, 2)
vq_mma_kernel() {
    extern __shared__ __align__(128) char sm[];
    const unsigned smb = (unsigned)__cvta_generic_to_shared(sm);

    const int tid  = threadIdx.x;
    const int lane = tid & 31;
    const int wid  = tid >> 5;
    const int wm   = wid >> 2;        // 0..1
    const int wn   = wid & 3;         // 0..3
    const int mblk = blockIdx.x >> 6;
    const int nblk = blockIdx.x & 63;

    const __nv_bfloat16* Ahg = g_Ah + (size_t)(mblk * MT) * C_DIM;
    const __nv_bfloat16* Bhg = g_Bh + (size_t)(nblk * NT) * C_DIM;

    const unsigned axor  = (unsigned)(lane & 7) << 4;
    const unsigned aoff  = (unsigned)(((lane & 7) + ((lane >> 3) & 1) * 8) * 128);
    const unsigned acolb = (unsigned)(((lane >> 4) & 1) * 16);
    const unsigned boff  = (unsigned)(((lane & 7) + ((lane >> 4) & 1) * 8) * 128);
    const unsigned bcolb = (unsigned)(((lane >> 3) & 1) * 16);

    float acc[4][4][4];
#pragma unroll
    for (int mt = 0; mt < 4; mt++)
#pragma unroll
        for (int nf = 0; nf < 4; nf++)
#pragma unroll
            for (int r = 0; r < 4; r++) acc[mt][nf][r] = 0.0f;

    auto load_stage = [&](int st, int k0) {
        const unsigned sb0 = smb + (unsigned)st * STAGE_BYTES;
#pragma unroll
        for (int i = 0; i < 4; i++) {
            int g = tid + 256 * i;
            int row = g >> 3;
            int c = g & 7;
            unsigned off = (unsigned)(row * 128) +
                           (((unsigned)(c * 16)) ^ ((unsigned)(row & 7) << 4));
            const size_t so = (size_t)row * C_DIM + k0 + c * 8;
            cpa16(sb0 + off, Ahg + so);
            cpa16(sb0 + TILE_BYTES + off, Bhg + so);
        }
        asm volatile("cp.async.commit_group;" ::: "memory");
    };

    load_stage(0, 0);

    for (int c = 0; c < NCHUNK; c++) {
        const int st = c & 1;
        if (c + 1 < NCHUNK) {
            load_stage(st ^ 1, (c + 1) * KC);
            asm volatile("cp.async.wait_group 1;" ::: "memory");
        } else {
            asm volatile("cp.async.wait_group 0;" ::: "memory");
        }
        __syncthreads();

        const unsigned sa = smb + (unsigned)st * STAGE_BYTES;
        const unsigned sb = sa + TILE_BYTES;
#pragma unroll
        for (int ks = 0; ks < 4; ks++) {
            unsigned af[4][4];
#pragma unroll
            for (int mt = 0; mt < 4; mt++) {
                unsigned addr = sa + (unsigned)((wm * 64 + mt * 16) * 128) + aoff
                                + (((unsigned)(ks * 32) + acolb) ^ axor);
                ldsm4(af[mt][0], af[mt][1], af[mt][2], af[mt][3], addr);
            }
            unsigned bf[4][2];
#pragma unroll
            for (int g2 = 0; g2 < 2; g2++) {
                unsigned addr = sb + (unsigned)((wn * 32 + g2 * 16) * 128) + boff
                                + (((unsigned)(ks * 32) + bcolb) ^ axor);
                ldsm4(bf[g2 * 2][0], bf[g2 * 2][1],
                      bf[g2 * 2 + 1][0], bf[g2 * 2 + 1][1], addr);
            }
#pragma unroll
            for (int mt = 0; mt < 4; mt++)
#pragma unroll
                for (int nf = 0; nf < 4; nf++)
                    MMA_BF16(acc[mt][nf], af[mt], bf[nf]);
        }
        __syncthreads();
    }

    // ---- epilogue: s = ee - 2*dot -> sortable key; store + per-row min ----
    unsigned* sRed = (unsigned*)sm;   // [4][128]
#pragma unroll
    for (int mt = 0; mt < 4; mt++) {
#pragma unroll
        for (int rh = 0; rh < 2; rh++) {
            const int mloc = wm * 64 + mt * 16 + (lane >> 2) + rh * 8;
            const size_t row = (size_t)(mblk * MT + mloc);
            unsigned kmin = 0xFFFFFFFFu;
#pragma unroll
            for (int nf = 0; nf < 4; nf++) {
                const int n0 = nblk * NT + wn * 32 + nf * 8 + (lane & 3) * 2;
                float s0 = fmaf(-2.0f, acc[mt][nf][rh * 2 + 0], __ldg(&g_ee[n0]));
                float s1 = fmaf(-2.0f, acc[mt][nf][rh * 2 + 1], __ldg(&g_ee[n0 + 1]));
                unsigned k0 = skey(s0), k1 = skey(s1);
                ((unsigned*)g_S)[row * (NE / 2) + (n0 >> 1)] = k0 | (k1 << 16);
                if (k0 < kmin) kmin = k0;
                if (k1 < kmin) kmin = k1;
            }
#pragma unroll
            for (int o = 1; o <= 2; o <<= 1) {
                unsigned ov = __shfl_xor_sync(0xffffffffu, kmin, o);
                if (ov < kmin) kmin = ov;
            }
            if ((lane & 3) == 0) sRed[wn * 128 + mloc] = kmin;
        }
    }
    __syncthreads();
    if (tid < 128) {
        unsigned b = sRed[tid];
#pragma unroll
        for (int w = 1; w < 4; w++) {
            unsigned v = sRed[w * 128 + tid];
            if (v < b) b = v;
        }
        atomicMin(&g_amin[mblk * MT + tid], b);
    }
}

// ---------------- resolve: scan keys, exact fp32 on candidates ----------------
__global__ void __launch_bounds__(256)
vq_resolve_kernel(const float* __restrict__ cb) {
    const int row  = blockIdx.x * 8 + (threadIdx.x >> 5);
    const int lane = threadIdx.x & 31;

    const unsigned km = g_amin[row];
    const float ub = skey_inv((km << 16) | 0xFFFFu);        // upper edge of min bucket
    const unsigned thr = skey(ub + 2.0f * g_eps[row]);
    const unsigned thr2 = thr * 0x10001u;

    float zreg[16];
    {
        const float4* zp = (const float4*)(g_zt + (size_t)row * C_DIM + lane * 16);
#pragma unroll
        for (int q = 0; q < 4; q++) {
            float4 v = zp[q];
            zreg[q * 4 + 0] = v.x; zreg[q * 4 + 1] = v.y;
            zreg[q * 4 + 2] = v.z; zreg[q * 4 + 3] = v.w;
        }
    }
    const float zz = g_zz[row];

    unsigned long long best = ~0ull;
    const uint4* srow = (const uint4*)(g_S + (size_t)row * NE);
    for (int it = 0; it < 32; it++) {
        uint4 x = srow[lane + 32 * it];
        unsigned mn = __vminu2(__vminu2(x.x, x.y), __vminu2(x.z, x.w));
        bool any = (__vcmpleu2(mn, thr2) != 0u);
        unsigned bm = __ballot_sync(0xffffffffu, any);
        while (bm) {
            int src = __ffs(bm) - 1; bm &= bm - 1;
            unsigned ws[4];
            ws[0] = __shfl_sync(0xffffffffu, x.x, src);
            ws[1] = __shfl_sync(0xffffffffu, x.y, src);
            ws[2] = __shfl_sync(0xffffffffu, x.z, src);
            ws[3] = __shfl_sync(0xffffffffu, x.w, src);
#pragma unroll
            for (int e = 0; e < 8; e++) {
                unsigned kv = (ws[e >> 1] >> ((e & 1) * 16)) & 0xFFFFu;
                if (kv <= thr) {
                    const int j = (src + 32 * it) * 8 + e;
                    const float4* cp = (const float4*)(cb + (size_t)j * C_DIM + lane * 16);
                    float d = 0.0f;
#pragma unroll
                    for (int q = 0; q < 4; q++) {
                        float4 cv = __ldg(cp + q);
                        d = fmaf(zreg[q * 4 + 0], cv.x, d);
                        d = fmaf(zreg[q * 4 + 1], cv.y, d);
                        d = fmaf(zreg[q * 4 + 2], cv.z, d);
                        d = fmaf(zreg[q * 4 + 3], cv.w, d);
                    }
#pragma unroll
                    for (int o = 16; o; o >>= 1) d += __shfl_xor_sync(0xffffffffu, d, o);
                    float ve = __fsub_rn(__fadd_rn(zz, __ldg(&g_ee[j])), 2.0f * d);
                    unsigned long long pv =
                        ((unsigned long long)__float_as_uint(ve) << 32) | (unsigned)j;
                    if (pv < best) best = pv;
                }
            }
        }
    }
    if (lane == 0) g_best[row] = best;
}

// ---------------- output (coalesced via zt) + loss partials ----------------
__global__ void __launch_bounds__(256)
vq_output_kernel(const float* __restrict__ m, const float* __restrict__ cb,
                 float* __restrict__ out) {
    __shared__ float red[8];
    const int warp = threadIdx.x >> 5;
    const int lane = threadIdx.x & 31;
    const int row = blockIdx.x * 8 + warp;
    const int idx = (int)(g_best[row] & 0xffffffffu);

    const float4* zp = (const float4*)(g_zt + (size_t)row * C_DIM);
    const float4* cp = (const float4*)(cb + (size_t)idx * C_DIM);
    float4* op = (float4*)(out + (size_t)row * C_DIM);

    float ssq = 0.0f;
#pragma unroll
    for (int i = 0; i < 4; i++) {
        float4 zv = zp[lane + 32 * i];
        float4 cv = __ldg(cp + lane + 32 * i);
        float4 o;
        float t;
        t = cv.x - zv.x; ssq = fmaf(t, t, ssq); o.x = zv.x + t;
        t = cv.y - zv.y; ssq = fmaf(t, t, ssq); o.y = zv.y + t;
        t = cv.z - zv.z; ssq = fmaf(t, t, ssq); o.z = zv.z + t;
        t = cv.w - zv.w; ssq = fmaf(t, t, ssq); o.w = zv.w + t;
        op[lane + 32 * i] = o;
    }
#pragma unroll
    for (int o = 16; o; o >>= 1) ssq += __shfl_xor_sync(0xffffffffu, ssq, o);
    if (lane == 0) red[warp] = (m[row] == 0.0f) ? ssq : 0.0f;
    __syncthreads();
    if (threadIdx.x == 0) {
        float s = 0.0f;
#pragma unroll
        for (int w = 0; w < 8; w++) s += red[w];
        atomicAdd(&g_sumsq, s);
    }
}

// ---------------- write idx (as float) and the scalar loss --------------
__global__ void vq_finalize_kernel(float* __restrict__ out) {
    int n = blockIdx.x * blockDim.x + threadIdx.x;
    if (n < N_ROWS)
        out[(size_t)N_ROWS * C_DIM + 1 + n] = (float)(int)(g_best[n] & 0xffffffffu);
    if (n == 0) {
        float denom = g_sumw * (float)C_DIM;
        out[(size_t)N_ROWS * C_DIM] = (1.0f + BETA_F) * g_sumsq / denom;
    }
}

// ---------------- launch ----------------
extern "C" void kernel_launch(void* const* d_in, const int* in_sizes, int n_in,
                              void* d_out, int out_size) {
    (void)in_sizes; (void)n_in; (void)out_size;
    const float* z  = (const float*)d_in[0];
    const float* m  = (const float*)d_in[1];
    const float* cb = (const float*)d_in[2];
    float* out = (float*)d_out;

    cudaFuncSetAttribute(vq_mma_kernel,
                         cudaFuncAttributeMaxDynamicSharedMemorySize, SMEM_TOTAL);

    vq_init_kernel<<<N_ROWS / 256, 256>>>();
    vq_zz_kernel<<<N_ROWS / 256, 256>>>(z, m);
    vq_ee_kernel<<<NE * 32 / 256, 256>>>(cb);
    vq_zsplit_kernel<<<4096, 256>>>(z);
    vq_cbsplit_kernel<<<NE * C_DIM / 256, 256>>>(cb);
    vq_mma_kernel<<<MBLK * NBLK, 256, SMEM_TOTAL>>>();
    vq_resolve_kernel<<<N_ROWS / 8, 256>>>(cb);
    vq_output_kernel<<<N_ROWS / 8, 256>>>(m, cb, out);
    vq_finalize_kernel<<<N_ROWS / 256, 256>>>(out);
}